// round 6
// baseline (speedup 1.0000x reference)
#include <cuda_runtime.h>
#include <cuda_bf16.h>
#include <stdint.h>

// Resubmission of the Round-3 candidate — previous bench failed in infra
// (container failed twice), kernel never evaluated.

// ---------------------------------------------------------------------------
// Problem constants
// ---------------------------------------------------------------------------
#define QDIM   4096
#define NDIM   8192
#define DDIM   256
#define KSPLIT 768          // split-bf16 K: A=[hi|hi|lo], B=[hi|lo|hi]
#define BM     128
#define BN     256
#define BK     64
#define NKT    12           // 768/64
#define STAGES 3
#define NITER  10

// ---------------------------------------------------------------------------
// Device scratch (no allocation allowed)
// ---------------------------------------------------------------------------
__device__ __align__(128) __nv_bfloat16 g_A[(size_t)QDIM * KSPLIT];   // 6.3 MB
__device__ __align__(128) __nv_bfloat16 g_B[(size_t)NDIM * KSPLIT];   // 12.6 MB
__device__ __align__(128) float g_q2[QDIM];
__device__ __align__(128) float g_n2[NDIM];
__device__ __align__(128) float g_w[(size_t)QDIM * NDIM];             // 128 MB

// ---------------------------------------------------------------------------
// PTX helpers (sm_80-era features only — final target is plain sm_100)
// ---------------------------------------------------------------------------
__device__ __forceinline__ uint32_t smem_to_u32(const void* p) {
    uint32_t a;
    asm("{ .reg .u64 t; cvta.to.shared.u64 t, %1; cvt.u32.u64 %0, t; }"
        : "=r"(a) : "l"(p));
    return a;
}

__device__ __forceinline__ void cpasync16(uint32_t dst, const void* src) {
    asm volatile("cp.async.cg.shared.global [%0], [%1], 16;"
                 :: "r"(dst), "l"(src) : "memory");
}
__device__ __forceinline__ void cp_commit() {
    asm volatile("cp.async.commit_group;" ::: "memory");
}
template <int N> __device__ __forceinline__ void cp_wait() {
    asm volatile("cp.async.wait_group %0;" :: "n"(N) : "memory");
}

__device__ __forceinline__ void ldmatrix_x4(uint32_t* r, uint32_t addr) {
    asm volatile("ldmatrix.sync.aligned.m8n8.x4.shared.b16 {%0,%1,%2,%3}, [%4];"
                 : "=r"(r[0]), "=r"(r[1]), "=r"(r[2]), "=r"(r[3]) : "r"(addr));
}

__device__ __forceinline__ void mma_bf16(float* c, const uint32_t* a,
                                         const uint32_t* b) {
    asm volatile(
        "mma.sync.aligned.m16n8k16.row.col.f32.bf16.bf16.f32 "
        "{%0,%1,%2,%3}, {%4,%5,%6,%7}, {%8,%9}, {%0,%1,%2,%3};"
        : "+f"(c[0]), "+f"(c[1]), "+f"(c[2]), "+f"(c[3])
        : "r"(a[0]), "r"(a[1]), "r"(a[2]), "r"(a[3]), "r"(b[0]), "r"(b[1]));
}

// ---------------------------------------------------------------------------
// Kernel 1: fp32 row norms + split-bf16 operand build. One warp per row.
// grid = (QDIM+NDIM)/8 blocks of 256 threads
// ---------------------------------------------------------------------------
__global__ void __launch_bounds__(256)
prep_kernel(const float* __restrict__ query, const float* __restrict__ neigh) {
    int warp = (blockIdx.x * 256 + threadIdx.x) >> 5;   // 0..12287
    int l = threadIdx.x & 31;
    bool isQ = warp < QDIM;
    int r = isQ ? warp : warp - QDIM;
    const float4* src = (const float4*)(isQ ? query + (size_t)r * DDIM
                                            : neigh + (size_t)r * DDIM);
    __nv_bfloat16* dst = isQ ? g_A + (size_t)r * KSPLIT
                             : g_B + (size_t)r * KSPLIT;

    float4 v0 = src[l];        // elems [l*4 .. l*4+4)
    float4 v1 = src[l + 32];   // elems [128 + l*4 ..)

    float s = v0.x * v0.x + v0.y * v0.y + v0.z * v0.z + v0.w * v0.w
            + v1.x * v1.x + v1.y * v1.y + v1.z * v1.z + v1.w * v1.w;

    float f0[4] = {v0.x, v0.y, v0.z, v0.w};
    float f1[4] = {v1.x, v1.y, v1.z, v1.w};
    __nv_bfloat16 h0[4], l0[4], h1[4], l1[4];
#pragma unroll
    for (int i = 0; i < 4; ++i) {
        h0[i] = __float2bfloat16(f0[i]);
        l0[i] = __float2bfloat16(f0[i] - __bfloat162float(h0[i]));
        h1[i] = __float2bfloat16(f1[i]);
        l1[i] = __float2bfloat16(f1[i] - __bfloat162float(h1[i]));
    }
    // pack 4 bf16 -> 8B
    uint2 H0, L0, H1, L1;
    {
        __nv_bfloat162 a(h0[0], h0[1]), b(h0[2], h0[3]);
        H0 = make_uint2(*(uint32_t*)&a, *(uint32_t*)&b);
        __nv_bfloat162 c(l0[0], l0[1]), d(l0[2], l0[3]);
        L0 = make_uint2(*(uint32_t*)&c, *(uint32_t*)&d);
        __nv_bfloat162 e(h1[0], h1[1]), f(h1[2], h1[3]);
        H1 = make_uint2(*(uint32_t*)&e, *(uint32_t*)&f);
        __nv_bfloat162 g(l1[0], l1[1]), h(l1[2], l1[3]);
        L1 = make_uint2(*(uint32_t*)&g, *(uint32_t*)&h);
    }
    int b0 = l * 4;        // within segment, first 128-elem half
    int b1 = 128 + l * 4;  // second half
    // segment 0: hi
    *(uint2*)(dst + b0) = H0;
    *(uint2*)(dst + b1) = H1;
    if (isQ) {  // A'' = [hi | hi | lo]
        *(uint2*)(dst + 256 + b0) = H0;
        *(uint2*)(dst + 256 + b1) = H1;
        *(uint2*)(dst + 512 + b0) = L0;
        *(uint2*)(dst + 512 + b1) = L1;
    } else {    // B'' = [hi | lo | hi]
        *(uint2*)(dst + 256 + b0) = L0;
        *(uint2*)(dst + 256 + b1) = L1;
        *(uint2*)(dst + 512 + b0) = H0;
        *(uint2*)(dst + 512 + b1) = H1;
    }

#pragma unroll
    for (int off = 16; off > 0; off >>= 1)
        s += __shfl_xor_sync(0xffffffffu, s, off);
    if (l == 0) {
        if (isQ) g_q2[r] = s; else g_n2[r] = s;
    }
}

// ---------------------------------------------------------------------------
// Kernel 2: HMMA bf16 GEMM (128x256 tile, K=768) + fused epilogue -> g_w
// 256 threads, 8 warps as 2(M) x 4(N); warp tile 64x64
// ---------------------------------------------------------------------------
#define A_BYTES (BM * 128)                         // 16 KB
#define B_BYTES (BN * 128)                         // 32 KB
#define STAGE_BYTES (A_BYTES + B_BYTES)            // 48 KB
#define SMEM_DYN (STAGES * STAGE_BYTES)            // 144 KB

__device__ __forceinline__ void load_tile(uint32_t abuf, uint32_t bbuf,
                                          int kt, int qbase, int nbase,
                                          int tid) {
    const char* gA = (const char*)g_A + ((size_t)qbase * KSPLIT + (size_t)kt * BK) * 2;
    const char* gB = (const char*)g_B + ((size_t)nbase * KSPLIT + (size_t)kt * BK) * 2;
    // A: 1024 16B-units (128 rows x 8), 4 per thread
#pragma unroll
    for (int i = 0; i < 4; ++i) {
        int g = tid * 4 + i;
        int r = g >> 3, ku = g & 7;
        uint32_t so = (uint32_t)(r * 128 + ((ku ^ (r & 7)) << 4));
        cpasync16(abuf + so, gA + (size_t)r * (KSPLIT * 2) + (size_t)ku * 16);
    }
    // B: 2048 16B-units (256 rows x 8), 8 per thread
#pragma unroll
    for (int i = 0; i < 8; ++i) {
        int g = tid * 8 + i;
        int r = g >> 3, ku = g & 7;
        uint32_t so = (uint32_t)(r * 128 + ((ku ^ (r & 7)) << 4));
        cpasync16(bbuf + so, gB + (size_t)r * (KSPLIT * 2) + (size_t)ku * 16);
    }
}

__global__ void __launch_bounds__(256, 1)
gemm_kernel(const float* __restrict__ gumbel) {
    extern __shared__ char smem_raw[];
    uint32_t sbase = smem_to_u32(smem_raw);

    int tid = threadIdx.x;
    int wid = tid >> 5;
    int l   = tid & 31;
    int warpm = wid & 1;          // 0..1 -> 64-row slab
    int warpn = wid >> 1;         // 0..3 -> 64-col slab

    int nbase = blockIdx.x * BN;
    int qbase = blockIdx.y * BM;

    uint32_t abuf[STAGES], bbuf[STAGES];
#pragma unroll
    for (int s = 0; s < STAGES; ++s) {
        abuf[s] = sbase + s * STAGE_BYTES;
        bbuf[s] = abuf[s] + A_BYTES;
    }

    // prologue: tiles 0,1 into stages 0,1
    load_tile(abuf[0], bbuf[0], 0, qbase, nbase, tid);
    cp_commit();
    load_tile(abuf[1], bbuf[1], 1, qbase, nbase, tid);
    cp_commit();

    float acc[4][8][4];
#pragma unroll
    for (int mt = 0; mt < 4; ++mt)
#pragma unroll
        for (int nt = 0; nt < 8; ++nt)
#pragma unroll
            for (int i = 0; i < 4; ++i) acc[mt][nt][i] = 0.f;

    int a_lr = (l & 15);
    int a_ku = (l >> 4);
    int b_lr = ((l >> 4) << 3) + (l & 7);
    int b_ku = ((l >> 3) & 1);

    int cur = 0, ldst = 2;
#pragma unroll 1
    for (int kt = 0; kt < NKT; ++kt) {
        cp_wait<1>();
        __syncthreads();
        if (kt + 2 < NKT)
            load_tile(abuf[ldst], bbuf[ldst], kt + 2, qbase, nbase, tid);
        cp_commit();

        uint32_t aS = abuf[cur], bS = bbuf[cur];
#pragma unroll
        for (int ks = 0; ks < 4; ++ks) {
            int kb = ks * 2;
            uint32_t afr[4][4];
#pragma unroll
            for (int mt = 0; mt < 4; ++mt) {
                int r = warpm * 64 + mt * 16 + a_lr;
                uint32_t addr = aS + r * 128 + (((kb + a_ku) ^ (r & 7)) << 4);
                ldmatrix_x4(afr[mt], addr);
            }
            uint32_t bfr[4][4];
#pragma unroll
            for (int bt = 0; bt < 4; ++bt) {
                int r = warpn * 64 + bt * 16 + b_lr;
                uint32_t addr = bS + r * 128 + (((kb + b_ku) ^ (r & 7)) << 4);
                ldmatrix_x4(bfr[bt], addr);
            }
#pragma unroll
            for (int mt = 0; mt < 4; ++mt)
#pragma unroll
                for (int nt = 0; nt < 8; ++nt)
                    mma_bf16(acc[mt][nt], afr[mt], &bfr[nt >> 1][(nt & 1) * 2]);
        }
        if (++cur == STAGES) cur = 0;
        if (++ldst == STAGES) ldst = 0;
    }
    cp_wait<0>();

    // Fused epilogue: w = gumbel - sqrt(max(q2 + n2 - 2*dot, 0))
    {
        int row0 = qbase + warpm * 64 + (l >> 2);
        int colb = nbase + warpn * 64 + (l & 3) * 2;
#pragma unroll
        for (int mt = 0; mt < 4; ++mt) {
            int rA = row0 + mt * 16;
            int rB = rA + 8;
            float q2a = __ldg(&g_q2[rA]);
            float q2b = __ldg(&g_q2[rB]);
            const float* gAraw = gumbel + (size_t)rA * NDIM;
            const float* gBraw = gumbel + (size_t)rB * NDIM;
            float* wA = g_w + (size_t)rA * NDIM;
            float* wB = g_w + (size_t)rB * NDIM;
#pragma unroll
            for (int nt = 0; nt < 8; ++nt) {
                int col = colb + nt * 8;
                float n2a = __ldg(&g_n2[col]);
                float n2b = __ldg(&g_n2[col + 1]);
                float2 ga = *(const float2*)(gAraw + col);
                float2 gb = *(const float2*)(gBraw + col);
                float2 oa, ob;
                oa.x = ga.x - sqrtf(fmaxf(fmaf(-2.f, acc[mt][nt][0], q2a + n2a), 0.f));
                oa.y = ga.y - sqrtf(fmaxf(fmaf(-2.f, acc[mt][nt][1], q2a + n2b), 0.f));
                ob.x = gb.x - sqrtf(fmaxf(fmaf(-2.f, acc[mt][nt][2], q2b + n2a), 0.f));
                ob.y = gb.y - sqrtf(fmaxf(fmaf(-2.f, acc[mt][nt][3], q2b + n2b), 0.f));
                *(float2*)(wA + col) = oa;
                *(float2*)(wB + col) = ob;
            }
        }
    }
}

// ---------------------------------------------------------------------------
// Kernel 3: iterative relaxed top-k; one block (512 thr) per query row
//   e = exp(w - m); 10x { p = e/sum; khot += p; e *= max(1-p, tiny) }
// double-buffered reduction scratch -> 1 syncthreads per stage
// ---------------------------------------------------------------------------
__global__ void __launch_bounds__(512)
iter_kernel(float* __restrict__ out) {
    __shared__ float sred[2][16];

    int t = threadIdx.x;
    int w = t >> 5, l = t & 31;
    const float4* wrow = (const float4*)(g_w + (size_t)blockIdx.x * NDIM);
    float4* orow = (float4*)(out + (size_t)blockIdx.x * NDIM);

    float4 v[4];
    float mx = -3.4e38f;
#pragma unroll
    for (int i = 0; i < 4; ++i) {
        v[i] = wrow[i * 512 + t];
        mx = fmaxf(mx, fmaxf(fmaxf(v[i].x, v[i].y), fmaxf(v[i].z, v[i].w)));
    }
#pragma unroll
    for (int o = 16; o > 0; o >>= 1)
        mx = fmaxf(mx, __shfl_xor_sync(0xffffffffu, mx, o));
    if (l == 0) sred[0][w] = mx;
    __syncthreads();
    float M = sred[0][0];
#pragma unroll
    for (int j = 1; j < 16; ++j) M = fmaxf(M, sred[0][j]);

    float e[16], kh[16];
#pragma unroll
    for (int i = 0; i < 4; ++i) {
        e[i * 4 + 0] = __expf(v[i].x - M);
        e[i * 4 + 1] = __expf(v[i].y - M);
        e[i * 4 + 2] = __expf(v[i].z - M);
        e[i * 4 + 3] = __expf(v[i].w - M);
    }
#pragma unroll
    for (int j = 0; j < 16; ++j) kh[j] = 0.f;

#pragma unroll
    for (int it = 0; it < NITER; ++it) {
        int buf = (it + 1) & 1;   // alternate; max pass used buf 0
        float s = 0.f;
#pragma unroll
        for (int j = 0; j < 16; ++j) s += e[j];
#pragma unroll
        for (int o = 16; o > 0; o >>= 1)
            s += __shfl_xor_sync(0xffffffffu, s, o);
        if (l == 0) sred[buf][w] = s;
        __syncthreads();
        float tot = sred[buf][0];
#pragma unroll
        for (int j = 1; j < 16; ++j) tot += sred[buf][j];
        float inv = 1.0f / tot;
#pragma unroll
        for (int j = 0; j < 16; ++j) {
            float p = e[j] * inv;
            kh[j] += p;
            e[j] *= fmaxf(1.0f - p, 1.1754944e-38f);
        }
    }

#pragma unroll
    for (int i = 0; i < 4; ++i) {
        float4 o4;
        o4.x = kh[i * 4 + 0];
        o4.y = kh[i * 4 + 1];
        o4.z = kh[i * 4 + 2];
        o4.w = kh[i * 4 + 3];
        orow[i * 512 + t] = o4;
    }
}

// ---------------------------------------------------------------------------
// Launch
// ---------------------------------------------------------------------------
extern "C" void kernel_launch(void* const* d_in, const int* in_sizes, int n_in,
                              void* d_out, int out_size) {
    const float* query  = (const float*)d_in[0];   // [4096, 256]
    const float* neigh  = (const float*)d_in[1];   // [1, 8192, 256]
    const float* gumbel = (const float*)d_in[2];   // [4096, 8192]
    float* out = (float*)d_out;                    // [4096, 8192]

    prep_kernel<<<(QDIM + NDIM) / 8, 256>>>(query, neigh);

    cudaFuncSetAttribute(gemm_kernel,
                         cudaFuncAttributeMaxDynamicSharedMemorySize, SMEM_DYN);
    dim3 grid(NDIM / BN, QDIM / BM);
    gemm_kernel<<<grid, 256, SMEM_DYN>>>(gumbel);

    iter_kernel<<<QDIM, 512>>>(out);
}

// round 7
// speedup vs baseline: 1.8568x; 1.8568x over previous
#include <cuda_runtime.h>
#include <cuda_fp16.h>
#include <stdint.h>

// Round 6: plain-fp16 GEMM (K=256). Round-3/6 evidence: legacy mma.sync on
// sm_100 saturates at ~135 TF/s regardless of tile shape -> cut MACs 3x by
// dropping the split-bf16 K=768 trick. fp16 (11-bit mantissa) direct product
// gives predicted rel_err ~2e-4 (5x under the 1e-3 gate).

// ---------------------------------------------------------------------------
#define QDIM   4096
#define NDIM   8192
#define DDIM   256
#define BM     128
#define BN     128
#define BK     64
#define NKT    4            // 256/64
#define STAGES 3
#define NITER  10

// ---------------------------------------------------------------------------
// Device scratch (no allocation allowed)
// ---------------------------------------------------------------------------
__device__ __align__(128) __half g_A[(size_t)QDIM * DDIM];            // 2 MB
__device__ __align__(128) __half g_B[(size_t)NDIM * DDIM];            // 4 MB
__device__ __align__(128) float g_q2[QDIM];
__device__ __align__(128) float g_n2[NDIM];
__device__ __align__(128) float g_w[(size_t)QDIM * NDIM];             // 128 MB

// ---------------------------------------------------------------------------
// PTX helpers (sm_80-era features only — final target is plain sm_100)
// ---------------------------------------------------------------------------
__device__ __forceinline__ uint32_t smem_to_u32(const void* p) {
    uint32_t a;
    asm("{ .reg .u64 t; cvta.to.shared.u64 t, %1; cvt.u32.u64 %0, t; }"
        : "=r"(a) : "l"(p));
    return a;
}

__device__ __forceinline__ void cpasync16(uint32_t dst, const void* src) {
    asm volatile("cp.async.cg.shared.global [%0], [%1], 16;"
                 :: "r"(dst), "l"(src) : "memory");
}
__device__ __forceinline__ void cp_commit() {
    asm volatile("cp.async.commit_group;" ::: "memory");
}
template <int N> __device__ __forceinline__ void cp_wait() {
    asm volatile("cp.async.wait_group %0;" :: "n"(N) : "memory");
}

__device__ __forceinline__ void ldmatrix_x4(uint32_t* r, uint32_t addr) {
    asm volatile("ldmatrix.sync.aligned.m8n8.x4.shared.b16 {%0,%1,%2,%3}, [%4];"
                 : "=r"(r[0]), "=r"(r[1]), "=r"(r[2]), "=r"(r[3]) : "r"(addr));
}

__device__ __forceinline__ void mma_fp16(float* c, const uint32_t* a,
                                         const uint32_t* b) {
    asm volatile(
        "mma.sync.aligned.m16n8k16.row.col.f32.f16.f16.f32 "
        "{%0,%1,%2,%3}, {%4,%5,%6,%7}, {%8,%9}, {%0,%1,%2,%3};"
        : "+f"(c[0]), "+f"(c[1]), "+f"(c[2]), "+f"(c[3])
        : "r"(a[0]), "r"(a[1]), "r"(a[2]), "r"(a[3]), "r"(b[0]), "r"(b[1]));
}

// ---------------------------------------------------------------------------
// Kernel 1: fp32 row norms + fp16 convert. One warp per row.
// grid = (QDIM+NDIM)/8 blocks of 256 threads; each thread: 8 elems
// ---------------------------------------------------------------------------
__global__ void __launch_bounds__(256)
prep_kernel(const float* __restrict__ query, const float* __restrict__ neigh) {
    int warp = (blockIdx.x * 256 + threadIdx.x) >> 5;   // 0..12287
    int l = threadIdx.x & 31;
    bool isQ = warp < QDIM;
    int r = isQ ? warp : warp - QDIM;
    const float4* src = (const float4*)(isQ ? query + (size_t)r * DDIM
                                            : neigh + (size_t)r * DDIM);
    __half* dst = isQ ? g_A + (size_t)r * DDIM : g_B + (size_t)r * DDIM;

    float4 v0 = src[l * 2];       // elems [l*8 .. l*8+4)
    float4 v1 = src[l * 2 + 1];   // elems [l*8+4 .. l*8+8)

    float s = v0.x * v0.x + v0.y * v0.y + v0.z * v0.z + v0.w * v0.w
            + v1.x * v1.x + v1.y * v1.y + v1.z * v1.z + v1.w * v1.w;

    __half2 h0 = __floats2half2_rn(v0.x, v0.y);
    __half2 h1 = __floats2half2_rn(v0.z, v0.w);
    __half2 h2 = __floats2half2_rn(v1.x, v1.y);
    __half2 h3 = __floats2half2_rn(v1.z, v1.w);
    uint4 pk;
    pk.x = *(uint32_t*)&h0; pk.y = *(uint32_t*)&h1;
    pk.z = *(uint32_t*)&h2; pk.w = *(uint32_t*)&h3;
    ((uint4*)dst)[l] = pk;

#pragma unroll
    for (int off = 16; off > 0; off >>= 1)
        s += __shfl_xor_sync(0xffffffffu, s, off);
    if (l == 0) {
        if (isQ) g_q2[r] = s; else g_n2[r] = s;
    }
}

// ---------------------------------------------------------------------------
// Kernel 2: HMMA fp16 GEMM (128x128 tile, K=256) + fused epilogue -> g_w
// 256 threads, 8 warps as 4(M) x 2(N); warp tile 32x64; 2 CTAs/SM
// ---------------------------------------------------------------------------
#define A_BYTES (BM * 128)                         // 16 KB
#define B_BYTES (BN * 128)                         // 16 KB
#define STAGE_BYTES (A_BYTES + B_BYTES)            // 32 KB
#define SMEM_DYN (STAGES * STAGE_BYTES)            // 96 KB

__device__ __forceinline__ void load_tile(uint32_t abuf, uint32_t bbuf,
                                          int kt, int qbase, int nbase,
                                          int tid) {
    const char* gA = (const char*)g_A + ((size_t)qbase * DDIM + (size_t)kt * BK) * 2;
    const char* gB = (const char*)g_B + ((size_t)nbase * DDIM + (size_t)kt * BK) * 2;
    // A and B: 1024 16B-units each (128 rows x 8 units); 4 per thread each
#pragma unroll
    for (int i = 0; i < 4; ++i) {
        int g = tid * 4 + i;
        int r = g >> 3, ku = g & 7;
        uint32_t so = (uint32_t)(r * 128 + ((ku ^ (r & 7)) << 4));
        cpasync16(abuf + so, gA + (size_t)r * (DDIM * 2) + (size_t)ku * 16);
        cpasync16(bbuf + so, gB + (size_t)r * (DDIM * 2) + (size_t)ku * 16);
    }
}

__global__ void __launch_bounds__(256, 2)
gemm_kernel(const float* __restrict__ gumbel) {
    extern __shared__ char smem_raw[];
    uint32_t sbase = smem_to_u32(smem_raw);

    int tid = threadIdx.x;
    int wid = tid >> 5;
    int l   = tid & 31;
    int warpm = wid & 3;          // 0..3 -> 32-row slab
    int warpn = wid >> 2;         // 0..1 -> 64-col slab

    int nbase = blockIdx.x * BN;
    int qbase = blockIdx.y * BM;

    uint32_t abuf[STAGES], bbuf[STAGES];
#pragma unroll
    for (int s = 0; s < STAGES; ++s) {
        abuf[s] = sbase + s * STAGE_BYTES;
        bbuf[s] = abuf[s] + A_BYTES;
    }

    // prologue: tiles 0,1 into stages 0,1
    load_tile(abuf[0], bbuf[0], 0, qbase, nbase, tid);
    cp_commit();
    load_tile(abuf[1], bbuf[1], 1, qbase, nbase, tid);
    cp_commit();

    float acc[2][8][4];
#pragma unroll
    for (int mt = 0; mt < 2; ++mt)
#pragma unroll
        for (int nt = 0; nt < 8; ++nt)
#pragma unroll
            for (int i = 0; i < 4; ++i) acc[mt][nt][i] = 0.f;

    int a_lr = (l & 15);
    int a_ku = (l >> 4);
    int b_lr = ((l >> 4) << 3) + (l & 7);
    int b_ku = ((l >> 3) & 1);

#pragma unroll
    for (int kt = 0; kt < NKT; ++kt) {
        const int s = kt % STAGES;
        if (kt < NKT - 2)       cp_wait<1>();
        else if (kt == NKT - 2) cp_wait<1>();
        else                    cp_wait<0>();
        __syncthreads();
        if (kt + 2 < NKT) {
            load_tile(abuf[(kt + 2) % STAGES], bbuf[(kt + 2) % STAGES],
                      kt + 2, qbase, nbase, tid);
            cp_commit();
        }

        uint32_t aS = abuf[s], bS = bbuf[s];
#pragma unroll
        for (int ks = 0; ks < 4; ++ks) {
            int kb = ks * 2;
            uint32_t afr[2][4];
#pragma unroll
            for (int mt = 0; mt < 2; ++mt) {
                int r = warpm * 32 + mt * 16 + a_lr;
                uint32_t addr = aS + r * 128 + (((kb + a_ku) ^ (r & 7)) << 4);
                ldmatrix_x4(afr[mt], addr);
            }
            uint32_t bfr[4][4];
#pragma unroll
            for (int bt = 0; bt < 4; ++bt) {
                int r = warpn * 64 + bt * 16 + b_lr;
                uint32_t addr = bS + r * 128 + (((kb + b_ku) ^ (r & 7)) << 4);
                ldmatrix_x4(bfr[bt], addr);
            }
#pragma unroll
            for (int mt = 0; mt < 2; ++mt)
#pragma unroll
                for (int nt = 0; nt < 8; ++nt)
                    mma_fp16(acc[mt][nt], afr[mt], &bfr[nt >> 1][(nt & 1) * 2]);
        }
        __syncthreads();
    }

    // Fused epilogue: w = gumbel - sqrt(max(q2 + n2 - 2*dot, 0))
    {
        int row0 = qbase + warpm * 32 + (l >> 2);
        int colb = nbase + warpn * 64 + (l & 3) * 2;
#pragma unroll
        for (int mt = 0; mt < 2; ++mt) {
            int rA = row0 + mt * 16;
            int rB = rA + 8;
            float q2a = __ldg(&g_q2[rA]);
            float q2b = __ldg(&g_q2[rB]);
            const float* gAraw = gumbel + (size_t)rA * NDIM;
            const float* gBraw = gumbel + (size_t)rB * NDIM;
            float* wA = g_w + (size_t)rA * NDIM;
            float* wB = g_w + (size_t)rB * NDIM;
#pragma unroll
            for (int nt = 0; nt < 8; ++nt) {
                int col = colb + nt * 8;
                float n2a = __ldg(&g_n2[col]);
                float n2b = __ldg(&g_n2[col + 1]);
                float2 ga = *(const float2*)(gAraw + col);
                float2 gb = *(const float2*)(gBraw + col);
                float2 oa, ob;
                oa.x = ga.x - sqrtf(fmaxf(fmaf(-2.f, acc[mt][nt][0], q2a + n2a), 0.f));
                oa.y = ga.y - sqrtf(fmaxf(fmaf(-2.f, acc[mt][nt][1], q2a + n2b), 0.f));
                ob.x = gb.x - sqrtf(fmaxf(fmaf(-2.f, acc[mt][nt][2], q2b + n2a), 0.f));
                ob.y = gb.y - sqrtf(fmaxf(fmaf(-2.f, acc[mt][nt][3], q2b + n2b), 0.f));
                *(float2*)(wA + col) = oa;
                *(float2*)(wB + col) = ob;
            }
        }
    }
}

// ---------------------------------------------------------------------------
// Kernel 3: iterative relaxed top-k; one block (512 thr) per query row
//   e = exp(w - m); 10x { p = e/sum; khot += p; e *= max(1-p, tiny) }
// ---------------------------------------------------------------------------
__global__ void __launch_bounds__(512)
iter_kernel(float* __restrict__ out) {
    __shared__ float sred[2][16];

    int t = threadIdx.x;
    int w = t >> 5, l = t & 31;
    const float4* wrow = (const float4*)(g_w + (size_t)blockIdx.x * NDIM);
    float4* orow = (float4*)(out + (size_t)blockIdx.x * NDIM);

    float4 v[4];
    float mx = -3.4e38f;
#pragma unroll
    for (int i = 0; i < 4; ++i) {
        v[i] = wrow[i * 512 + t];
        mx = fmaxf(mx, fmaxf(fmaxf(v[i].x, v[i].y), fmaxf(v[i].z, v[i].w)));
    }
#pragma unroll
    for (int o = 16; o > 0; o >>= 1)
        mx = fmaxf(mx, __shfl_xor_sync(0xffffffffu, mx, o));
    if (l == 0) sred[0][w] = mx;
    __syncthreads();
    float M = sred[0][0];
#pragma unroll
    for (int j = 1; j < 16; ++j) M = fmaxf(M, sred[0][j]);

    float e[16], kh[16];
#pragma unroll
    for (int i = 0; i < 4; ++i) {
        e[i * 4 + 0] = __expf(v[i].x - M);
        e[i * 4 + 1] = __expf(v[i].y - M);
        e[i * 4 + 2] = __expf(v[i].z - M);
        e[i * 4 + 3] = __expf(v[i].w - M);
    }
#pragma unroll
    for (int j = 0; j < 16; ++j) kh[j] = 0.f;

#pragma unroll
    for (int it = 0; it < NITER; ++it) {
        int buf = (it + 1) & 1;   // alternate; max pass used buf 0
        float s = 0.f;
#pragma unroll
        for (int j = 0; j < 16; ++j) s += e[j];
#pragma unroll
        for (int o = 16; o > 0; o >>= 1)
            s += __shfl_xor_sync(0xffffffffu, s, o);
        if (l == 0) sred[buf][w] = s;
        __syncthreads();
        float tot = sred[buf][0];
#pragma unroll
        for (int j = 1; j < 16; ++j) tot += sred[buf][j];
        float inv = 1.0f / tot;
#pragma unroll
        for (int j = 0; j < 16; ++j) {
            float p = e[j] * inv;
            kh[j] += p;
            e[j] *= fmaxf(1.0f - p, 1.1754944e-38f);
        }
    }

#pragma unroll
    for (int i = 0; i < 4; ++i) {
        float4 o4;
        o4.x = kh[i * 4 + 0];
        o4.y = kh[i * 4 + 1];
        o4.z = kh[i * 4 + 2];
        o4.w = kh[i * 4 + 3];
        orow[i * 512 + t] = o4;
    }
}

// ---------------------------------------------------------------------------
// Launch
// ---------------------------------------------------------------------------
extern "C" void kernel_launch(void* const* d_in, const int* in_sizes, int n_in,
                              void* d_out, int out_size) {
    const float* query  = (const float*)d_in[0];   // [4096, 256]
    const float* neigh  = (const float*)d_in[1];   // [1, 8192, 256]
    const float* gumbel = (const float*)d_in[2];   // [4096, 8192]
    float* out = (float*)d_out;                    // [4096, 8192]

    prep_kernel<<<(QDIM + NDIM) / 8, 256>>>(query, neigh);

    cudaFuncSetAttribute(gemm_kernel,
                         cudaFuncAttributeMaxDynamicSharedMemorySize, SMEM_DYN);
    dim3 grid(NDIM / BN, QDIM / BM);
    gemm_kernel<<<grid, 256, SMEM_DYN>>>(gumbel);

    iter_kernel<<<QDIM, 512>>>(out);
}